// round 15
// baseline (speedup 1.0000x reference)
#include <cuda_runtime.h>
#include <math.h>
#include <stdint.h>

// NF4 quantize-dequantize, straight-through forward: out = data_type[idx]*s,
// s = per-row max|x| (clip 1e-6), idx = searchsorted(boundaries, x/s, left).
//
// R13 (3rd submit; prior runs were container-acquisition failures; source
// audited for hangs: no inter-block waits, uniform barriers, monotone claims)
// = R12 (winner, 104.4us) + two changes:
//  - Prefetch lead widened to a full iteration: the claimed-next row rn is
//    held in a register across iterations and prefetched at the LOOP TOP
//    (overlapping pass A of r, whose reads are L2 hits from the previous
//    prefetch). The claim for rn2 happens during the reduce.
//  - Fused LDS.64 table entry {T, vlo} + separate Vhi[k] loaded under
//    predicate only when x > T (~3% of elements; T=+inf on the 243
//    non-boundary cells): halves table LDS instructions/wavefronts.
// Proven and kept: row in registers (16/thread @ NT=512), 3 blocks/SM,
// dynamic row claiming, .cs streaming stores, exact threshold construction.
//
// Exactness (proven): thresholds T_j = largest float with RN(t/s) <= b_j
// (nextafter-refined) => (x/s > b_j) == (x > T_j) bit-exact. 258-cell LUT
// over u = x*(128/s)+129 via magic-FMA; cell width s/128 << min threshold
// gap (~0.085*s) => <=1 threshold per cell.

#define COLS   8192
#define NF4    2048          // float4 per row
#define NT     512
#define CH     4             // float4 per thread per row (2048/512)
#define NB     15
#define NL     16
#define NCELL  258
#define GRID   444           // 3 blocks/SM x 148 SMs

__device__ int g_row_counter;

__global__ void init_counter_kernel(int start) { g_row_counter = start; }

__device__ __forceinline__ void stg_cs(float4* p, float4 v) {
    asm volatile("st.global.cs.v4.f32 [%0], {%1,%2,%3,%4};"
                 :: "l"(p), "f"(v.x), "f"(v.y), "f"(v.z), "f"(v.w) : "memory");
}
__device__ __forceinline__ void prefetch_l2(const void* p) {
    asm volatile("prefetch.global.L2 [%0];" :: "l"(p));
}

__global__ __launch_bounds__(NT, 3)
void nf4_kernel(const float* __restrict__ x,
                const float* __restrict__ bnd,
                const float* __restrict__ dt,
                float* __restrict__ out,
                int rows)
{
    __shared__ float2 TV[NCELL];          // {T, vlo} per cell (LDS.64)
    __shared__ float Vhi[NCELL];          // vhi, loaded only when x > T
    __shared__ float Tsm[NB];
    __shared__ float Vsm[NL];
    __shared__ float wmax[NT / 32];
    __shared__ int rnS;

    const int tid = threadIdx.x;
    const int lane = tid & 31;
    const float4* __restrict__ xv = (const float4*)x;
    float4* __restrict__ ov = (float4*)out;
    const float MAGIC = 8388608.0f + 129.0f;   // 2^23 + 129

    int r = blockIdx.x;                 // launcher guarantees grid <= rows
    if (r >= rows) return;

    // prologue: claim the row we'll do after r
    if (tid == 64) rnS = atomicAdd(&g_row_counter, 1);
    __syncthreads();
    int rn = rnS;

    while (true) {
        // ---- loop top: prefetch next row (full-iteration lead) ----
        if (rn < rows) {
            const char* np = (const char*)(xv + (size_t)rn * NF4);
            prefetch_l2(np + (size_t)tid * 64);   // 512 thr x 64B = 32KB row
        }

        // ---- pass A: row -> registers, fused absmax (L2 hits after iter 1) ----
        float4 va[CH];
        float m = 0.0f;
        {
            const float4* rp = xv + (size_t)r * NF4;
#pragma unroll
            for (int i = 0; i < CH; i++) {
                va[i] = __ldg(rp + tid + i * NT);
                m = fmaxf(m, fmaxf(fmaxf(fabsf(va[i].x), fabsf(va[i].y)),
                                   fmaxf(fabsf(va[i].z), fabsf(va[i].w))));
            }
        }
        if (tid == 64) rnS = atomicAdd(&g_row_counter, 1);   // claim next-next
#pragma unroll
        for (int o = 16; o; o >>= 1) m = fmaxf(m, __shfl_xor_sync(0xffffffffu, m, o));
        if (lane == 0) wmax[tid >> 5] = m;
        __syncthreads();    // also: prev iter's table readers are done
        float s;
        {
            float t0 = fmaxf(fmaxf(wmax[0], wmax[1]),  fmaxf(wmax[2], wmax[3]));
            float t1 = fmaxf(fmaxf(wmax[4], wmax[5]),  fmaxf(wmax[6], wmax[7]));
            float t2 = fmaxf(fmaxf(wmax[8], wmax[9]),  fmaxf(wmax[10], wmax[11]));
            float t3 = fmaxf(fmaxf(wmax[12], wmax[13]), fmaxf(wmax[14], wmax[15]));
            s = fmaxf(fmaxf(t0, t1), fmaxf(t2, t3));
        }
        s = fmaxf(s, 1e-6f);            // jnp.clip(..., 1e-6)
        const float c1 = __fdiv_rn(128.0f, s);
        const int rn2 = rnS;

        // ---- exact raw-x thresholds + scaled levels ----
        if (tid < NB) {
            const float mid = __ldg(bnd + tid);
            float t = mid * s;
            for (int it = 0; it < 8 && __fdiv_rn(t, s) <= mid; it++)
                t = nextafterf(t, __int_as_float(0x7f800000));
            for (int it = 0; it < 8 && __fdiv_rn(t, s) > mid; it++)
                t = nextafterf(t, __int_as_float(0xff800000));
            Tsm[tid] = t;
        }
        if (tid >= 32 && tid < 32 + NL)
            Vsm[tid - 32] = __ldg(dt + tid - 32) * s;   // RN, matches dt[idx]*s
        __syncthreads();

        // ---- build LUT: fused {T, vlo} + rare vhi ----
        if (tid < NCELL) {
            const float w = s * 0.0078125f;   // s/128
            const float padc = 0.05f * w;
            const float L = ((float)tid - 129.5f) * w - padc;
            const float R = ((float)tid - 128.5f) * w + padc;
            int jb = 0;
#pragma unroll
            for (int jj = 0; jj < NB; jj++) jb += (Tsm[jj] < L) ? 1 : 0;
            float T = __int_as_float(0x7f800000);
            float vlo, vhi;
            if (jb < NB && Tsm[jb] <= R) {
                T = Tsm[jb]; vlo = Vsm[jb]; vhi = Vsm[jb + 1];
            } else {
                vlo = vhi = Vsm[jb];
            }
            TV[tid] = make_float2(T, vlo);
            Vhi[tid] = vhi;
        }
        __syncthreads();

        // ---- pass B: quantize from registers, streaming-store ----
        {
            float4* wp = ov + (size_t)r * NF4;
#pragma unroll
            for (int i = 0; i < CH; i++) {
                const float4 b = va[i];
                float4 q;
                {
                    const int k = __float_as_int(fmaf(b.x, c1, MAGIC)) & 0x3ff;
                    const float2 e = TV[k];
                    q.x = e.y;
                    if (b.x > e.x) q.x = Vhi[k];
                }
                {
                    const int k = __float_as_int(fmaf(b.y, c1, MAGIC)) & 0x3ff;
                    const float2 e = TV[k];
                    q.y = e.y;
                    if (b.y > e.x) q.y = Vhi[k];
                }
                {
                    const int k = __float_as_int(fmaf(b.z, c1, MAGIC)) & 0x3ff;
                    const float2 e = TV[k];
                    q.z = e.y;
                    if (b.z > e.x) q.z = Vhi[k];
                }
                {
                    const int k = __float_as_int(fmaf(b.w, c1, MAGIC)) & 0x3ff;
                    const float2 e = TV[k];
                    q.w = e.y;
                    if (b.w > e.x) q.w = Vhi[k];
                }
                stg_cs(wp + tid + i * NT, q);
            }
        }

        if (rn >= rows) break;
        r = rn;
        rn = rn2;
    }
}

extern "C" void kernel_launch(void* const* d_in, const int* in_sizes, int n_in,
                              void* d_out, int out_size)
{
    const float* x = nullptr;
    const float* bnd = nullptr;
    const float* dt = nullptr;
    long long nx = 0;
    for (int i = 0; i < n_in; i++) {
        if (in_sizes[i] == NB)      bnd = (const float*)d_in[i];
        else if (in_sizes[i] == NL) dt  = (const float*)d_in[i];
        else { x = (const float*)d_in[i]; nx = in_sizes[i]; }
    }
    const int rows = (int)(nx / COLS);
    const int grid = rows < GRID ? rows : GRID;

    init_counter_kernel<<<1, 1>>>(grid);   // rows [0, grid) claimed statically
    nf4_kernel<<<grid, NT>>>(x, bnd, dt, (float*)d_out, rows);
}